// round 14
// baseline (speedup 1.0000x reference)
#include <cuda_runtime.h>
#include <math.h>
#include <stdint.h>

// ---------------------------------------------------------------------------
// FedTGPClientLoss:
//   ce    = mean_b [ logsumexp(logits[b,:]) - logits[b, label_b] ]   (0 if !finite)
//   proto = mean_b mean_d (features[b,d] - protos[label_b, d])^2
//   total = ce + proto                                               (ce if !finite)
// Output: [total, ce, proto]  (3 x f32)
//
// Byte-level descendant of the 25.1us winner (one warp/row, register v[8],
// two-pass max-subtracted logsumexp, fused threadfence grid reduction) with
// the label-dependency chain broken up:
//   - probe + both label-dtype candidates issued as independent loads
//   - feature loads join the logits batch (label-independent)
//   - only proto loads + label logit wait on the resolved label, and their
//     latency overlaps the max/exp compute.
// ---------------------------------------------------------------------------

#define MAXBLK 8192
__device__ double   g_pce[MAXBLK];
__device__ double   g_pms[MAXBLK];
__device__ unsigned g_count = 0;   // reset by the last block each call

#define NEG_INF (-__int_as_float(0x7f800000))

__global__ __launch_bounds__(256) void row_kernel(
    const float* __restrict__ logits,
    const int*   __restrict__ l32,     // labels viewed as int32 words
    const float* __restrict__ features,
    const float* __restrict__ protos,
    float* __restrict__ out,
    int B, int C, int D)
{
    const int lane = threadIdx.x & 31;
    const int wid  = threadIdx.x >> 5;
    const int row  = blockIdx.x * 8 + wid;
    const bool active = (row < B);

    float ce_f = 0.0f, ms_f = 0.0f;

    if (active) {
        const float* lr = logits + (size_t)row * C;
        const float4* lrow = (const float4*)lr;
        const int C4 = C >> 2;
        const int Ctail = C & 3;
        const int D4 = D >> 2;

        // ---- issue ALL label-independent loads up front ----
        // dtype probe + both label candidates (independent of each other):
        //   int64 labels < C => all odd (high) words are 0.
        //   int32 labels uniform [0,C) => P(32 odd words all zero) ~ C^-32 ~ 0.
        int probe = l32[2 * lane + 1];
        int cand64 = l32[2 * row];        // label if int64
        int cand32 = l32[row];            // label if int32

        if (C4 <= 256 && D4 == 128) {
            // ============ fast path =================================
            // logits batch (8 x LDG.128)
            float4 v[8];
            #pragma unroll
            for (int j = 0; j < 8; j++) {
                int idx = j * 32 + lane;
                v[j] = (idx < C4) ? lrow[idx]
                                  : make_float4(NEG_INF, NEG_INF, NEG_INF, NEG_INF);
            }
            float tval = (lane < Ctail) ? lr[C4 * 4 + lane] : NEG_INF;

            // feature batch (label-independent, 4 x LDG.128)
            const float4* frow = (const float4*)(features + (size_t)row * D);
            float4 f[4];
            #pragma unroll
            for (int j = 0; j < 4; j++) f[j] = frow[j * 32 + lane];

            // ---- resolve label (parallel candidates), then proto loads ----
            bool lbl64 = (__ballot_sync(0xFFFFFFFFu, probe != 0) == 0u);
            const int label = lbl64 ? cand64 : cand32;

            const float4* prow = (const float4*)(protos + (size_t)label * D);
            float4 p[4];
            #pragma unroll
            for (int j = 0; j < 4; j++) p[j] = prow[j * 32 + lane];
            const float lbl_logit = __ldg(lr + label);   // L1-hot line

            // ---- two-pass logsumexp on register-resident row ----
            float m = NEG_INF;
            #pragma unroll
            for (int j = 0; j < 8; j++)
                m = fmaxf(m, fmaxf(fmaxf(v[j].x, v[j].y), fmaxf(v[j].z, v[j].w)));
            m = fmaxf(m, tval);

            #pragma unroll
            for (int off = 16; off > 0; off >>= 1)
                m = fmaxf(m, __shfl_xor_sync(0xFFFFFFFFu, m, off));

            float s = 0.0f;
            #pragma unroll
            for (int j = 0; j < 8; j++) {
                s += __expf(v[j].x - m) + __expf(v[j].y - m)
                   + __expf(v[j].z - m) + __expf(v[j].w - m);  // exp(-inf)=0 pads
            }
            if (lane < Ctail) s += __expf(tval - m);

            // ---- MSE FMAs (p loads have had the exp phase to land) ----
            float sq = 0.0f;
            #pragma unroll
            for (int j = 0; j < 4; j++) {
                float dx = f[j].x - p[j].x, dy = f[j].y - p[j].y;
                float dz = f[j].z - p[j].z, dw = f[j].w - p[j].w;
                sq = fmaf(dx, dx, fmaf(dy, dy, fmaf(dz, dz, fmaf(dw, dw, sq))));
            }

            // ---- warp sum reductions ----
            #pragma unroll
            for (int off = 16; off > 0; off >>= 1) {
                s  += __shfl_xor_sync(0xFFFFFFFFu, s,  off);
                sq += __shfl_xor_sync(0xFFFFFFFFu, sq, off);
            }

            ce_f = (m + __logf(s)) - lbl_logit;
            ms_f = sq / (float)D;
        } else {
            // ============ generic path ============
            bool lbl64 = (__ballot_sync(0xFFFFFFFFu, probe != 0) == 0u);
            const int label = lbl64 ? cand64 : cand32;
            const float lbl_logit = __ldg(lr + label);

            float m = NEG_INF;
            for (int idx = lane; idx < C4; idx += 32) {
                float4 q = lrow[idx];
                m = fmaxf(m, fmaxf(fmaxf(q.x, q.y), fmaxf(q.z, q.w)));
            }
            if (lane < Ctail) m = fmaxf(m, lr[C4 * 4 + lane]);
            #pragma unroll
            for (int off = 16; off > 0; off >>= 1)
                m = fmaxf(m, __shfl_xor_sync(0xFFFFFFFFu, m, off));
            float s = 0.0f;
            for (int idx = lane; idx < C4; idx += 32) {
                float4 q = lrow[idx];
                s += __expf(q.x - m) + __expf(q.y - m)
                   + __expf(q.z - m) + __expf(q.w - m);
            }
            if (lane < Ctail) s += __expf(lr[C4 * 4 + lane] - m);

            const float4* frow = (const float4*)(features + (size_t)row   * D);
            const float4* prow = (const float4*)(protos   + (size_t)label * D);
            float sq = 0.0f;
            for (int idx = lane; idx < D4; idx += 32) {
                float4 ff = frow[idx];
                float4 pp = prow[idx];
                float dx = ff.x - pp.x, dy = ff.y - pp.y;
                float dz = ff.z - pp.z, dw = ff.w - pp.w;
                sq = fmaf(dx, dx, fmaf(dy, dy, fmaf(dz, dz, fmaf(dw, dw, sq))));
            }
            const int Dtail = D & 3;
            if (lane < Dtail) {
                float d = features[(size_t)row * D + D4 * 4 + lane]
                        - protos[(size_t)label * D + D4 * 4 + lane];
                sq = fmaf(d, d, sq);
            }

            #pragma unroll
            for (int off = 16; off > 0; off >>= 1) {
                s  += __shfl_xor_sync(0xFFFFFFFFu, s,  off);
                sq += __shfl_xor_sync(0xFFFFFFFFu, sq, off);
            }
            ce_f = (m + __logf(s)) - lbl_logit;
            ms_f = sq / (float)D;
        }
    }

    // ---- block reduction of the 8 warp results (doubles) ----
    __shared__ double sm_ce[8], sm_ms[8];
    __shared__ bool   s_is_last;
    if (lane == 0) { sm_ce[wid] = (double)ce_f; sm_ms[wid] = (double)ms_f; }
    __syncthreads();

    if (threadIdx.x == 0) {
        double bce = 0.0, bms = 0.0;
        #pragma unroll
        for (int j = 0; j < 8; j++) { bce += sm_ce[j]; bms += sm_ms[j]; }
        g_pce[blockIdx.x] = bce;
        g_pms[blockIdx.x] = bms;
        __threadfence();
        unsigned prev = atomicAdd(&g_count, 1u);
        s_is_last = (prev == gridDim.x - 1);
    }
    __syncthreads();

    // ---- last-arriving block: reduce L2-hot partials, emit outputs ----
    if (s_is_last) {
        const int tid = threadIdx.x;
        const int nb  = gridDim.x;
        double ce = 0.0, ms = 0.0;
        for (int i = tid; i < nb; i += 256) { ce += g_pce[i]; ms += g_pms[i]; }

        __shared__ double red[512];
        red[tid] = ce; red[256 + tid] = ms;
        __syncthreads();
        #pragma unroll
        for (int off = 128; off > 0; off >>= 1) {
            if (tid < off) {
                red[tid]       += red[tid + off];
                red[256 + tid] += red[256 + tid + off];
            }
            __syncthreads();
        }

        if (tid == 0) {
            float ce_loss = (float)(red[0] / (double)B);
            if (!isfinite(ce_loss)) ce_loss = 0.0f;
            float proto_loss = (float)(red[256] / (double)B);
            float total = ce_loss + proto_loss;
            if (!isfinite(total)) total = ce_loss;
            out[0] = total;
            out[1] = ce_loss;
            out[2] = proto_loss;
            g_count = 0;          // reset for next graph replay
        }
    }
}

extern "C" void kernel_launch(void* const* d_in, const int* in_sizes, int n_in,
                              void* d_out, int out_size) {
    const float* logits   = (const float*)d_in[0];
    const int*   labels   = (const int*)d_in[1];
    const float* features = (const float*)d_in[2];
    const float* protos   = (const float*)d_in[3];
    float* out = (float*)d_out;

    const int B = in_sizes[1];                 // 16384
    const int C = in_sizes[0] / B;             // 1000
    const int D = in_sizes[2] / B;             // 512

    const int blocks = (B + 7) / 8;            // one warp per row, 8 warps/block
    row_kernel<<<blocks, 256>>>(logits, labels, features, protos, out, B, C, D);
}

// round 15
// speedup vs baseline: 1.1457x; 1.1457x over previous
#include <cuda_runtime.h>
#include <math.h>
#include <stdint.h>

// ---------------------------------------------------------------------------
// FedTGPClientLoss:
//   ce    = mean_b [ logsumexp(logits[b,:]) - logits[b, label_b] ]   (0 if !finite)
//   proto = mean_b mean_d (features[b,d] - labels-proto)^2 mean
//   total = ce + proto                                               (ce if !finite)
// Output: [total, ce, proto]  (3 x f32)
//
// Byte-exact 25.1us winner (one warp per row, register-resident two-pass
// logsumexp, warp-shuffle reductions, fused threadfence grid reduction) with
// ONE change: both label-dtype candidate loads are issued before the ballot,
// removing the last serial L2 dependency at +2 short-lived registers.
// ---------------------------------------------------------------------------

#define MAXBLK 8192
__device__ double   g_pce[MAXBLK];
__device__ double   g_pms[MAXBLK];
__device__ unsigned g_count = 0;   // reset by the last block each call

#define NEG_INF (-__int_as_float(0x7f800000))

__global__ __launch_bounds__(256) void row_kernel(
    const float* __restrict__ logits,
    const int*   __restrict__ l32,     // labels viewed as int32 words
    const float* __restrict__ features,
    const float* __restrict__ protos,
    float* __restrict__ out,
    int B, int C, int D)
{
    const int lane = threadIdx.x & 31;
    const int wid  = threadIdx.x >> 5;
    const int row  = blockIdx.x * 8 + wid;
    const bool active = (row < B);

    float ce_f = 0.0f, ms_f = 0.0f;

    if (active) {
        // ---- per-warp label dtype detection (first 64 int32 words = 256B) ----
        // int64 labels < C  =>  all odd (high) words are 0.
        // int32 labels uniform [0,C)  =>  P(32 odd words all zero) ~ C^-32 ~ 0.
        // Both candidates issued BEFORE the ballot (independent loads).
        int probe  = l32[2 * lane + 1];
        int cand64 = l32[2 * row];
        int cand32 = l32[row];
        bool lbl64 = (__ballot_sync(0xFFFFFFFFu, probe != 0) == 0u);
        const int label = lbl64 ? cand64 : cand32;

        const float* lr = logits + (size_t)row * C;
        const float lbl_logit = __ldg(lr + label);   // warp-uniform broadcast

        const float4* lrow = (const float4*)lr;
        const int C4 = C >> 2;
        const int Ctail = C & 3;

        float m = NEG_INF;
        float s = 0.0f;

        if (C4 <= 256) {
            // ---- fast path: logits row register-resident (<=32 floats/lane) ----
            float4 v[8];
            #pragma unroll
            for (int j = 0; j < 8; j++) {
                int idx = j * 32 + lane;
                if (idx < C4) v[j] = lrow[idx];
                else          v[j] = make_float4(NEG_INF, NEG_INF, NEG_INF, NEG_INF);
                m = fmaxf(m, fmaxf(fmaxf(v[j].x, v[j].y), fmaxf(v[j].z, v[j].w)));
            }
            float tval = NEG_INF;
            if (lane < Ctail) { tval = lr[C4 * 4 + lane]; m = fmaxf(m, tval); }

            #pragma unroll
            for (int off = 16; off > 0; off >>= 1)
                m = fmaxf(m, __shfl_xor_sync(0xFFFFFFFFu, m, off));

            #pragma unroll
            for (int j = 0; j < 8; j++) {
                s += __expf(v[j].x - m) + __expf(v[j].y - m)
                   + __expf(v[j].z - m) + __expf(v[j].w - m);   // exp(-inf)=0 pads
            }
            if (lane < Ctail) s += __expf(tval - m);
        } else {
            // ---- generic fallback: two passes, second reloads (L1-hot) ----
            for (int idx = lane; idx < C4; idx += 32) {
                float4 q = lrow[idx];
                m = fmaxf(m, fmaxf(fmaxf(q.x, q.y), fmaxf(q.z, q.w)));
            }
            if (lane < Ctail) m = fmaxf(m, lr[C4 * 4 + lane]);
            #pragma unroll
            for (int off = 16; off > 0; off >>= 1)
                m = fmaxf(m, __shfl_xor_sync(0xFFFFFFFFu, m, off));
            for (int idx = lane; idx < C4; idx += 32) {
                float4 q = lrow[idx];
                s += __expf(q.x - m) + __expf(q.y - m)
                   + __expf(q.z - m) + __expf(q.w - m);
            }
            if (lane < Ctail) s += __expf(lr[C4 * 4 + lane] - m);
        }

        // ---- per-row proto MSE ----
        const float4* frow = (const float4*)(features + (size_t)row   * D);
        const float4* prow = (const float4*)(protos   + (size_t)label * D);
        const int D4 = D >> 2;
        float sq = 0.0f;
        #pragma unroll 4
        for (int idx = lane; idx < D4; idx += 32) {
            float4 f = frow[idx];
            float4 p = prow[idx];
            float dx = f.x - p.x, dy = f.y - p.y, dz = f.z - p.z, dw = f.w - p.w;
            sq = fmaf(dx, dx, fmaf(dy, dy, fmaf(dz, dz, fmaf(dw, dw, sq))));
        }
        {
            const int Dtail = D & 3;
            if (lane < Dtail) {
                float d = features[(size_t)row * D + D4 * 4 + lane]
                        - protos[(size_t)label * D + D4 * 4 + lane];
                sq = fmaf(d, d, sq);
            }
        }

        // ---- warp sum reductions ----
        #pragma unroll
        for (int off = 16; off > 0; off >>= 1) {
            s  += __shfl_xor_sync(0xFFFFFFFFu, s,  off);
            sq += __shfl_xor_sync(0xFFFFFFFFu, sq, off);
        }

        ce_f = (m + __logf(s)) - lbl_logit;
        ms_f = sq / (float)D;
    }

    // ---- block reduction of the 8 warp results (doubles) ----
    __shared__ double sm_ce[8], sm_ms[8];
    __shared__ bool   s_is_last;
    if (lane == 0) { sm_ce[wid] = (double)ce_f; sm_ms[wid] = (double)ms_f; }
    __syncthreads();

    if (threadIdx.x == 0) {
        double bce = 0.0, bms = 0.0;
        #pragma unroll
        for (int j = 0; j < 8; j++) { bce += sm_ce[j]; bms += sm_ms[j]; }
        g_pce[blockIdx.x] = bce;
        g_pms[blockIdx.x] = bms;
        __threadfence();
        unsigned prev = atomicAdd(&g_count, 1u);
        s_is_last = (prev == gridDim.x - 1);
    }
    __syncthreads();

    // ---- last-arriving block: reduce L2-hot partials, emit outputs ----
    if (s_is_last) {
        const int tid = threadIdx.x;
        const int nb  = gridDim.x;
        double ce = 0.0, ms = 0.0;
        for (int i = tid; i < nb; i += 256) { ce += g_pce[i]; ms += g_pms[i]; }

        __shared__ double red[512];
        red[tid] = ce; red[256 + tid] = ms;
        __syncthreads();
        #pragma unroll
        for (int off = 128; off > 0; off >>= 1) {
            if (tid < off) {
                red[tid]       += red[tid + off];
                red[256 + tid] += red[256 + tid + off];
            }
            __syncthreads();
        }

        if (tid == 0) {
            float ce_loss = (float)(red[0] / (double)B);
            if (!isfinite(ce_loss)) ce_loss = 0.0f;
            float proto_loss = (float)(red[256] / (double)B);
            float total = ce_loss + proto_loss;
            if (!isfinite(total)) total = ce_loss;
            out[0] = total;
            out[1] = ce_loss;
            out[2] = proto_loss;
            g_count = 0;          // reset for next graph replay
        }
    }
}

extern "C" void kernel_launch(void* const* d_in, const int* in_sizes, int n_in,
                              void* d_out, int out_size) {
    const float* logits   = (const float*)d_in[0];
    const int*   labels   = (const int*)d_in[1];
    const float* features = (const float*)d_in[2];
    const float* protos   = (const float*)d_in[3];
    float* out = (float*)d_out;

    const int B = in_sizes[1];                 // 16384
    const int C = in_sizes[0] / B;             // 1000
    const int D = in_sizes[2] / B;             // 512

    const int blocks = (B + 7) / 8;            // one warp per row, 8 warps/block
    row_kernel<<<blocks, 256>>>(logits, labels, features, protos, out, B, C, D);
}